// round 17
// baseline (speedup 1.0000x reference)
#include <cuda_runtime.h>
#include <cuda_fp16.h>

// LODs = int(16*(256/16)^(L/7)) = 16,23,35,52,78,115,172,256
// entries: 256, 529, 1225, 2704, 6084, 13225, 29584, 65536
// LODs 0-6 in smem as scaled __half2 (53607*4B = 214.4KB); LOD7 in L2 (fp32).
//
// 16-point warp tile, component-per-lane, NO shuffles:
//   lane l: point a = l>>1, component comp = l&1 (0 = x, 1 = y).
// Each lane computes all 8 indices, reads all 8 tables (x/y lane pairs hit
// identical addresses -> smem broadcast / LDG coalesce), keeps its component,
// and stores its 32B half-row with one st.global.cs.v8.f32. The warp's store
// is 1024B contiguous. Branch-free clamped pts prefetch as in R11.

#define SMEM_H2 53607
#define SMEM_BYTES (SMEM_H2 * 4)
#define SD (1.0f / 1024.0f)
#define SU 1024.0f
#define TPB 1024

// packed f32x2 scale-down: one mul.rn.f32x2 for both components
__device__ __forceinline__ float2 h2_to_f2_scaled(const __half2 h)
{
    const float2 v = __half22float2(h);
    unsigned long long a, r;
    asm("mov.b64 %0, {%1, %2};" : "=l"(a) : "f"(v.x), "f"(v.y));
    const unsigned long long sdp =
        ((unsigned long long)__float_as_uint(SD) << 32) | __float_as_uint(SD);
    asm("mul.rn.f32x2 %0, %1, %2;" : "=l"(r) : "l"(a), "l"(sdp));
    float2 o;
    asm("mov.b64 {%0, %1}, %2;" : "=f"(o.x), "=f"(o.y) : "l"(r));
    return o;
}

__device__ __forceinline__ void stg256(float* p,
                                       float r0, float r1, float r2, float r3,
                                       float r4, float r5, float r6, float r7)
{
    asm volatile("st.global.cs.v8.f32 [%0], {%1,%2,%3,%4,%5,%6,%7,%8};"
                 :: "l"(p), "f"(r0), "f"(r1), "f"(r2), "f"(r3),
                    "f"(r4), "f"(r5), "f"(r6), "f"(r7)
                 : "memory");
}

__global__ void __launch_bounds__(TPB, 1)
dense_grid_v8_kernel(const float2* __restrict__ pts,
                     const float2* __restrict__ cb0,
                     const float2* __restrict__ cb1,
                     const float2* __restrict__ cb2,
                     const float2* __restrict__ cb3,
                     const float2* __restrict__ cb4,
                     const float2* __restrict__ cb5,
                     const float2* __restrict__ cb6,
                     const float2* __restrict__ cb7,
                     float* __restrict__ out,
                     int n)
{
    extern __shared__ __half2 sh[];

    // ---- Stage LODs 0-6 into smem as scaled half2 (coalesced) ----
    {
        const float2* __restrict__ srcs[7] = {cb0, cb1, cb2, cb3, cb4, cb5, cb6};
        const int cnt[7] = {256, 529, 1225, 2704, 6084, 13225, 29584};
        const int off[7] = {0, 256, 785, 2010, 4714, 10798, 24023};
#pragma unroll
        for (int L = 0; L < 7; ++L) {
            const float2* src = srcs[L];
            __half2* dst = sh + off[L];
            const int cn = cnt[L];
            for (int j = threadIdx.x; j < cn; j += TPB) {
                const float2 v = __ldg(&src[j]);
                dst[j] = __floats2half2_rn(v.x * SU, v.y * SU);
            }
        }
    }
    __syncthreads();

    const int l = threadIdx.x & 31;
    const int a = l >> 1;            // point within the 16-point warp tile
    const bool yc = (l & 1);         // 0: x component (chunks 0,1), 1: y (2,3)

    // Each warp owns 16 consecutive points per iteration (n % 16 == 0).
    const int base0 = ((blockIdx.x * TPB + (threadIdx.x & ~31)) >> 1);
    const int stride = (gridDim.x * TPB) >> 1;   // points per sweep

    if (base0 >= n) return;

    // Prologue: point for the first iteration (2-way broadcast load).
    float2 p = __ldg(&pts[base0 + a]);

    for (int base = base0; base < n; base += stride) {
        // ---- Branch-free prefetch of next iteration's point ----
        const float2 pn = __ldg(&pts[min(base + stride + a, n - 1)]);

        const float px = p.x, py = p.y;
        // trunc == floor for nonneg; same single fp32 multiply as reference
        const int i0 = (int)(px * 15.0f)  + (int)(py * 15.0f)  * 16;
        const int i1 = (int)(px * 22.0f)  + (int)(py * 22.0f)  * 23;
        const int i2 = (int)(px * 34.0f)  + (int)(py * 34.0f)  * 35;
        const int i3 = (int)(px * 51.0f)  + (int)(py * 51.0f)  * 52;
        const int i4 = (int)(px * 77.0f)  + (int)(py * 77.0f)  * 78;
        const int i5 = (int)(px * 114.0f) + (int)(py * 114.0f) * 115;
        const int i6 = (int)(px * 171.0f) + (int)(py * 171.0f) * 172;
        const int i7 = (int)(px * 255.0f) + (int)(py * 255.0f) * 256;

        // Long-latency L2 gather first.
        const float2 g7 = __ldg(&cb7[i7]);

        // Smem gathers (x/y lane pairs hit identical addresses -> broadcast).
        const float2 f0 = h2_to_f2_scaled(sh[0     + i0]);
        const float2 f1 = h2_to_f2_scaled(sh[256   + i1]);
        const float2 f2 = h2_to_f2_scaled(sh[785   + i2]);
        const float2 f3 = h2_to_f2_scaled(sh[2010  + i3]);
        const float2 f4 = h2_to_f2_scaled(sh[4714  + i4]);
        const float2 f5 = h2_to_f2_scaled(sh[10798 + i5]);
        const float2 f6 = h2_to_f2_scaled(sh[24023 + i6]);

        const float v0 = yc ? f0.y : f0.x;
        const float v1 = yc ? f1.y : f1.x;
        const float v2 = yc ? f2.y : f2.x;
        const float v3 = yc ? f3.y : f3.x;
        const float v4 = yc ? f4.y : f4.x;
        const float v5 = yc ? f5.y : f5.x;
        const float v6 = yc ? f6.y : f6.x;
        const float v7 = yc ? g7.y : g7.x;

        // One 256-bit streaming store per lane; warp covers 1024B contiguous.
        stg256(out + (size_t)base * 16 + (size_t)l * 8,
               v0, v1, v2, v3, v4, v5, v6, v7);

        p = pn;
    }
}

extern "C" void kernel_launch(void* const* d_in, const int* in_sizes, int n_in,
                              void* d_out, int out_size)
{
    const float2* pts = (const float2*)d_in[0];
    const float2* cb0 = (const float2*)d_in[1];
    const float2* cb1 = (const float2*)d_in[2];
    const float2* cb2 = (const float2*)d_in[3];
    const float2* cb3 = (const float2*)d_in[4];
    const float2* cb4 = (const float2*)d_in[5];
    const float2* cb5 = (const float2*)d_in[6];
    const float2* cb6 = (const float2*)d_in[7];
    const float2* cb7 = (const float2*)d_in[8];
    float* out = (float*)d_out;

    const int n = in_sizes[0] / 2;

    static int sm_count = -1;
    if (sm_count < 0) {
        cudaFuncSetAttribute(dense_grid_v8_kernel,
                             cudaFuncAttributeMaxDynamicSharedMemorySize,
                             SMEM_BYTES);
        cudaDeviceGetAttribute(&sm_count, cudaDevAttrMultiProcessorCount, 0);
    }

    dense_grid_v8_kernel<<<sm_count, TPB, SMEM_BYTES>>>(
        pts, cb0, cb1, cb2, cb3, cb4, cb5, cb6, cb7, out, n);
}